// round 16
// baseline (speedup 1.0000x reference)
#include <cuda_runtime.h>
#include <cuda_fp16.h>
#include <math_constants.h>

#define BATCH  4
#define SEQ    2048
#define DIM    1024
#define NHEADS 16
#define HDIM   64
#define MROWS  (BATCH*SEQ)   // 8192

// ---------------------------------------------------------------------------
// Scratch (no cudaMalloc allowed)
// ---------------------------------------------------------------------------
__device__ __half gh_x [(size_t)MROWS * DIM];
__device__ __half gh_Wq[(size_t)DIM * DIM];
__device__ __half gh_Wk[(size_t)DIM * DIM];
__device__ __half gh_Wv[(size_t)DIM * DIM];
__device__ __half gh_Wo[(size_t)DIM * DIM];
__device__ __half g_Q [(size_t)MROWS * DIM];
__device__ __half g_K [(size_t)MROWS * DIM];
__device__ __half g_V [(size_t)MROWS * DIM];
__device__ __half g_C [(size_t)MROWS * DIM];

// ---------------------------------------------------------------------------
// helpers
// ---------------------------------------------------------------------------
__device__ __forceinline__ void mma16(float c[4], const unsigned a[4], const unsigned b[2]) {
    asm volatile(
        "mma.sync.aligned.m16n8k16.row.col.f32.f16.f16.f32 "
        "{%0,%1,%2,%3}, {%4,%5,%6,%7}, {%8,%9}, {%0,%1,%2,%3};\n"
        : "+f"(c[0]), "+f"(c[1]), "+f"(c[2]), "+f"(c[3])
        : "r"(a[0]), "r"(a[1]), "r"(a[2]), "r"(a[3]), "r"(b[0]), "r"(b[1]));
}
__device__ __forceinline__ void ldmx4(unsigned& r0, unsigned& r1, unsigned& r2, unsigned& r3,
                                      unsigned addr) {
    asm volatile("ldmatrix.sync.aligned.m8n8.x4.shared.b16 {%0,%1,%2,%3}, [%4];"
                 : "=r"(r0), "=r"(r1), "=r"(r2), "=r"(r3) : "r"(addr));
}
__device__ __forceinline__ void ldmx4t(unsigned& r0, unsigned& r1, unsigned& r2, unsigned& r3,
                                       unsigned addr) {
    asm volatile("ldmatrix.sync.aligned.m8n8.x4.trans.shared.b16 {%0,%1,%2,%3}, [%4];"
                 : "=r"(r0), "=r"(r1), "=r"(r2), "=r"(r3) : "r"(addr));
}
__device__ __forceinline__ void cpa16(unsigned dst, const void* src) {
    asm volatile("cp.async.cg.shared.global [%0], [%1], 16;\n" :: "r"(dst), "l"(src));
}
#define CP_COMMIT asm volatile("cp.async.commit_group;\n" ::: "memory")
#define CP_WAIT0  asm volatile("cp.async.wait_group 0;\n" ::: "memory")
#define CP_WAIT1  asm volatile("cp.async.wait_group 1;\n" ::: "memory")
#define CP_WAIT2  asm volatile("cp.async.wait_group 2;\n" ::: "memory")

__device__ __forceinline__ unsigned packh2(float a, float b) {
    unsigned r;
    asm("cvt.rn.f16x2.f32 %0, %1, %2;" : "=r"(r) : "f"(b), "f"(a));
    return r;
}
__device__ __forceinline__ float ex2(float x) {
    float y;
    asm("ex2.approx.ftz.f32 %0, %1;" : "=f"(y) : "f"(x));
    return y;
}

// ---------------------------------------------------------------------------
// one-time fp32->fp16: x + all 4 weights in ONE launch
// ---------------------------------------------------------------------------
#define XQ  (MROWS * DIM / 4)
#define WQ4 (DIM * DIM / 4)
__global__ void convall(const float* __restrict__ x,
                        const float* __restrict__ w0, const float* __restrict__ w1,
                        const float* __restrict__ w2, const float* __restrict__ w3,
                        __half* __restrict__ xh,
                        __half* __restrict__ d0, __half* __restrict__ d1,
                        __half* __restrict__ d2, __half* __restrict__ d3) {
    const int g = blockIdx.x * blockDim.x + threadIdx.x;
    const float* s;
    __half* d;
    int i;
    if (g < XQ) { s = x; d = xh; i = g << 2; }
    else {
        int gg = g - XQ;
        int seg = gg >> 18;
        i = (gg & 0x3FFFF) << 2;
        s = (seg == 0) ? w0 : (seg == 1) ? w1 : (seg == 2) ? w2 : w3;
        d = (seg == 0) ? d0 : (seg == 1) ? d1 : (seg == 2) ? d2 : d3;
    }
    float4 v = *(const float4*)&s[i];
    *(__half2*)&d[i]     = __floats2half2_rn(v.x, v.y);
    *(__half2*)&d[i + 2] = __floats2half2_rn(v.z, v.w);
}

// ---------------------------------------------------------------------------
// GEMM (R12/R15 config): block 128x128, kstep 32, 8 warps (32x64), 3-stage
// cp.async pipeline (WAIT1 steady state), x4 ldmatrix fragments.
// ---------------------------------------------------------------------------
#define LAH 40
#define LBH 136
#define A_SZH (128*LAH)
#define B_SZH (32*LBH)
#define GSTGH (A_SZH+B_SZH)     // 9472 halves
#define GEMM_SMEM (3*GSTGH*2)   // 56832 B

struct GemmCtx {
    int t, warp, lane, wm, wn;
    unsigned s0;
};

__device__ __forceinline__ void gemm_issue(const __half* Ag, const __half* Bg,
                                           unsigned sb, int a_r, int a_c,
                                           int b_r, int b_c, int ko) {
    cpa16(sb + (a_r * LAH + a_c) * 2,             Ag + ko);
    cpa16(sb + (a_r * LAH + a_c + 8) * 2,         Ag + ko + 8);
    cpa16(sb + (A_SZH + b_r * LBH + b_c) * 2,     Bg + (size_t)ko * DIM);
    cpa16(sb + (A_SZH + b_r * LBH + b_c + 8) * 2, Bg + (size_t)ko * DIM + 8);
    CP_COMMIT;
}

__device__ __forceinline__ void gemm_mainloop(
    const __half* __restrict__ Ag, const __half* __restrict__ Bg,
    const GemmCtx& cx, float acc[2][8][4])
{
    const int t = cx.t, lane = cx.lane;
    const int a_r = t >> 1, a_c = (t & 1) << 4;
    const int b_r = t >> 3, b_c = (t & 7) << 4;
    const unsigned s0 = cx.s0;

    gemm_issue(Ag, Bg, s0,             a_r, a_c, b_r, b_c, 0);
    gemm_issue(Ag, Bg, s0 + GSTGH * 2, a_r, a_c, b_r, b_c, 32);

    const int arow = lane & 15;
    const int akof = (lane & 16) >> 1;
    const int brow = (lane & 7) + ((lane >> 3) & 1) * 8;
    const int bsel = (lane >> 4) << 3;

    const int NIT = DIM >> 5;     // 32
    for (int it = 0; it < NIT; ++it) {
        if (it < NIT - 1) { CP_WAIT1; } else { CP_WAIT0; }
        __syncthreads();

        if (it + 2 < NIT) {
            const unsigned sb = s0 + ((it + 2) % 3) * GSTGH * 2;
            gemm_issue(Ag, Bg, sb, a_r, a_c, b_r, b_c, (it + 2) << 5);
        }

        const unsigned abase = s0 + (it % 3) * GSTGH * 2;
        const unsigned bbase = abase + A_SZH * 2;

#pragma unroll
        for (int ch = 0; ch < 2; ch++) {
            const int k0 = ch << 4;
            unsigned af[2][4], bf[8][2];
#pragma unroll
            for (int mt = 0; mt < 2; mt++) {
                unsigned addr = abase +
                    (((cx.wm + (mt << 4) + arow) * LAH) + k0 + akof) * 2;
                ldmx4(af[mt][0], af[mt][1], af[mt][2], af[mt][3], addr);
            }
#pragma unroll
            for (int nt = 0; nt < 8; nt += 2) {
                unsigned addr = bbase +
                    (((k0 + brow) * LBH) + cx.wn + (nt << 3) + bsel) * 2;
                ldmx4t(bf[nt][0], bf[nt][1], bf[nt + 1][0], bf[nt + 1][1], addr);
            }
#pragma unroll
            for (int mt = 0; mt < 2; mt++)
#pragma unroll
                for (int nt = 0; nt < 8; nt++)
                    mma16(acc[mt][nt], af[mt], bf[nt]);
        }
    }
}

// ---- fused QKV projection: grid (24, 64). Q pre-scaled by 0.125*log2(e).
__global__ __launch_bounds__(256, 2)
void gemm_qkv(const __half* __restrict__ xh,
              const __half* __restrict__ Wq, const __half* __restrict__ Wk,
              const __half* __restrict__ Wv,
              __half* __restrict__ Qo, __half* __restrict__ Ko,
              __half* __restrict__ Vo)
{
    extern __shared__ __half sh[];
    GemmCtx cx;
    cx.t = threadIdx.x; cx.warp = cx.t >> 5; cx.lane = cx.t & 31;
    cx.wm = (cx.warp >> 1) << 5; cx.wn = (cx.warp & 1) << 6;
    cx.s0 = (unsigned)__cvta_generic_to_shared(sh);

    const int widx = blockIdx.x >> 3;
    const int col0 = (blockIdx.x & 7) << 7;
    const int row0 = blockIdx.y << 7;
    const __half* B = (widx == 0) ? Wq : (widx == 1) ? Wk : Wv;
    __half*       C = (widx == 0) ? Qo : (widx == 1) ? Ko : Vo;
    const float scale = (widx == 0) ? 0.125f * 1.44269504f : 1.0f;

    float acc[2][8][4];
#pragma unroll
    for (int mt = 0; mt < 2; mt++)
#pragma unroll
        for (int nt = 0; nt < 8; nt++)
#pragma unroll
            for (int i = 0; i < 4; i++) acc[mt][nt][i] = 0.f;

    const int a_r = cx.t >> 1, a_c = (cx.t & 1) << 4;
    const int b_r = cx.t >> 3, b_c = (cx.t & 7) << 4;
    gemm_mainloop(xh + (size_t)(row0 + a_r) * DIM + a_c,
                  B + (size_t)b_r * DIM + col0 + b_c, cx, acc);

    const int lr = cx.lane >> 2, lc = cx.lane & 3;
#pragma unroll
    for (int nt = 0; nt < 8; nt++) {
        const int c = col0 + cx.wn + (nt << 3) + (lc << 1);
#pragma unroll
        for (int mt = 0; mt < 2; mt++) {
            const int r = row0 + cx.wm + (mt << 4) + lr;
#pragma unroll
            for (int hh = 0; hh < 2; hh++) {
                float a0 = acc[mt][nt][(hh << 1)] * scale;
                float a1 = acc[mt][nt][(hh << 1) + 1] * scale;
                *(__half2*)&C[(size_t)(r + (hh << 3)) * DIM + c] =
                    __floats2half2_rn(a0, a1);
            }
        }
    }
}

// ---- output projection: float out + bias. grid (8, 64)
__global__ __launch_bounds__(256, 2)
void gemm_out(const __half* __restrict__ A, const __half* __restrict__ B,
              const float* __restrict__ bias, float* __restrict__ Cf)
{
    extern __shared__ __half sh[];
    GemmCtx cx;
    cx.t = threadIdx.x; cx.warp = cx.t >> 5; cx.lane = cx.t & 31;
    cx.wm = (cx.warp >> 1) << 5; cx.wn = (cx.warp & 1) << 6;
    cx.s0 = (unsigned)__cvta_generic_to_shared(sh);

    const int col0 = blockIdx.x << 7;
    const int row0 = blockIdx.y << 7;

    float acc[2][8][4];
#pragma unroll
    for (int mt = 0; mt < 2; mt++)
#pragma unroll
        for (int nt = 0; nt < 8; nt++)
#pragma unroll
            for (int i = 0; i < 4; i++) acc[mt][nt][i] = 0.f;

    const int a_r = cx.t >> 1, a_c = (cx.t & 1) << 4;
    const int b_r = cx.t >> 3, b_c = (cx.t & 7) << 4;
    gemm_mainloop(A + (size_t)(row0 + a_r) * DIM + a_c,
                  B + (size_t)b_r * DIM + col0 + b_c, cx, acc);

    const int lr = cx.lane >> 2, lc = cx.lane & 3;
#pragma unroll
    for (int nt = 0; nt < 8; nt++) {
        const int c = col0 + cx.wn + (nt << 3) + (lc << 1);
        const float bx = bias[c], by = bias[c + 1];
#pragma unroll
        for (int mt = 0; mt < 2; mt++) {
            const int r = row0 + cx.wm + (mt << 4) + lr;
#pragma unroll
            for (int hh = 0; hh < 2; hh++) {
                *(float2*)&Cf[(size_t)(r + (hh << 3)) * DIM + c] =
                    make_float2(acc[mt][nt][(hh << 1)] + bx,
                                acc[mt][nt][(hh << 1) + 1] + by);
            }
        }
    }
}

// ---------------------------------------------------------------------------
// fp16 flash attention: no-max base-2 softmax with ex2/pack/lsum FUSED into
// the PV loop (MUFU overlaps HMMA). 128 q-rows/block, 8 warps, 3-stage
// 64-key KV pipeline, x4 ldmatrix.
// ---------------------------------------------------------------------------
#define LKH 72
#define LVH 72
#define QSZH (128*LKH)
#define KSZH (64*LKH)
#define VSZH (64*LVH)
#define STGH (KSZH+VSZH)
#define ATT_SMEM ((QSZH + 3*STGH)*2)   // 73728 B

__global__ __launch_bounds__(256)
void attn_h(const __half* __restrict__ Q, const __half* __restrict__ K,
            const __half* __restrict__ V, __half* __restrict__ O)
{
    extern __shared__ __half sh[];

    const int qt = (gridDim.x - 1) - blockIdx.x;
    const int h  = blockIdx.y, b = blockIdx.z;
    const int t    = threadIdx.x;
    const int warp = t >> 5, lane = t & 31;
    const int lr   = lane >> 2, lc = lane & 3;
    const int q0   = qt << 7, w16 = warp << 4;
    const int wrow0 = q0 + w16;

    const __half* Kb = K + (size_t)b * SEQ * DIM + h * HDIM;
    const __half* Vb = V + (size_t)b * SEQ * DIM + h * HDIM;
    const unsigned smu = (unsigned)__cvta_generic_to_shared(sh);

    const int kvr = t >> 2, kvc = (t & 3) << 4;
    const int last = 2 * qt + 1;

    {
        const __half* Qb = Q + ((size_t)(b * SEQ + q0)) * DIM + h * HDIM;
#pragma unroll
        for (int j = 0; j < 4; j++) {
            int id = t + (j << 8);
            int r = id >> 3, c = (id & 7) << 3;
            cpa16(smu + (r * LKH + c) * 2, &Qb[(size_t)r * DIM + c]);
        }
        CP_COMMIT;
#pragma unroll
        for (int s = 0; s < 2; s++) {
            const __half* Kt = Kb + ((size_t)(s << 6)) * DIM;
            const __half* Vt = Vb + ((size_t)(s << 6)) * DIM;
            const unsigned sb = smu + (QSZH + s * STGH) * 2;
            cpa16(sb + (kvr * LKH + kvc) * 2,            &Kt[(size_t)kvr * DIM + kvc]);
            cpa16(sb + (kvr * LKH + kvc + 8) * 2,        &Kt[(size_t)kvr * DIM + kvc + 8]);
            cpa16(sb + (KSZH + kvr * LVH + kvc) * 2,     &Vt[(size_t)kvr * DIM + kvc]);
            cpa16(sb + (KSZH + kvr * LVH + kvc + 8) * 2, &Vt[(size_t)kvr * DIM + kvc + 8]);
            CP_COMMIT;
        }
        CP_WAIT2;
    }
    __syncthreads();

    // Q A-fragments (ldmatrix.x4)
    unsigned qa[4][4];
    {
        const int arow = lane & 15;
        const int akof = (lane & 16) >> 1;
#pragma unroll
        for (int ch = 0; ch < 4; ch++) {
            unsigned addr = smu + (((w16 + arow) * LKH) + (ch << 4) + akof) * 2;
            ldmx4(qa[ch][0], qa[ch][1], qa[ch][2], qa[ch][3], addr);
        }
    }

    const int krow8 = lane & 7;
    const int ksel  = (lane >> 4) << 3;
    const int kk8   = lane & 8;
    const int vrow  = (lane & 7) + ((lane >> 3) & 1) * 8;

    float o[8][4];
#pragma unroll
    for (int nt = 0; nt < 8; nt++)
#pragma unroll
        for (int i = 0; i < 4; i++) o[nt][i] = 0.f;
    float lsum[2][2] = {{0.f, 0.f}, {0.f, 0.f}};

    for (int kt = 0; kt <= last; ++kt) {
        if (kt < last) { CP_WAIT1; } else { CP_WAIT0; }
        __syncthreads();

        if (kt + 2 <= last) {
            const __half* Kt = Kb + ((size_t)((kt + 2) << 6)) * DIM;
            const __half* Vt = Vb + ((size_t)((kt + 2) << 6)) * DIM;
            const unsigned sb = smu + (QSZH + ((kt + 2) % 3) * STGH) * 2;
            cpa16(sb + (kvr * LKH + kvc) * 2,            &Kt[(size_t)kvr * DIM + kvc]);
            cpa16(sb + (kvr * LKH + kvc + 8) * 2,        &Kt[(size_t)kvr * DIM + kvc + 8]);
            cpa16(sb + (KSZH + kvr * LVH + kvc) * 2,     &Vt[(size_t)kvr * DIM + kvc]);
            cpa16(sb + (KSZH + kvr * LVH + kvc + 8) * 2, &Vt[(size_t)kvr * DIM + kvc + 8]);
            CP_COMMIT;
        }

        const unsigned kbase = smu + (QSZH + (kt % 3) * STGH) * 2;
        const unsigned vbase = kbase + KSZH * 2;

        if ((kt << 6) <= wrow0 + 15) {
            // ---- S = Q K^T ----
            float sc[8][4];
#pragma unroll
            for (int nt = 0; nt < 8; nt++)
#pragma unroll
                for (int i = 0; i < 4; i++) sc[nt][i] = 0.f;
#pragma unroll
            for (int ch = 0; ch < 4; ch++) {
                const int k0 = ch << 4;
#pragma unroll
                for (int nt = 0; nt < 8; nt += 2) {
                    unsigned addr = kbase +
                        ((((nt << 3) + ksel + krow8) * LKH) + k0 + kk8) * 2;
                    unsigned b0[2], b1[2];
                    ldmx4(b0[0], b0[1], b1[0], b1[1], addr);
                    mma16(sc[nt],     qa[ch], b0);
                    mma16(sc[nt + 1], qa[ch], b1);
                }
            }

            const bool diag = (kt << 6) + 63 > wrow0;

            // ---- PV loop with FUSED mask/ex2/lsum/pack per n-group ----
#pragma unroll
            for (int g = 0; g < 4; g++) {
                // mask + exp the 8 P values this group consumes
#pragma unroll
                for (int q = 0; q < 2; q++) {
                    const int nt = 2 * g + q;
#pragma unroll
                    for (int i = 0; i < 4; i++) {
                        float s = sc[nt][i];
                        if (diag) {
                            int rr = wrow0 + lr + ((i >> 1) << 3);
                            int cc = (kt << 6) + (nt << 3) + (lc << 1) + (i & 1);
                            if (cc > rr) s = -CUDART_INF_F;
                        }
                        float p = ex2(s);
                        sc[nt][i] = p;
                        lsum[nt & 1][i >> 1] += p;
                    }
                }
                unsigned pa[4];
                pa[0] = packh2(sc[2 * g][0],     sc[2 * g][1]);
                pa[1] = packh2(sc[2 * g][2],     sc[2 * g][3]);
                pa[2] = packh2(sc[2 * g + 1][0], sc[2 * g + 1][1]);
                pa[3] = packh2(sc[2 * g + 1][2], sc[2 * g + 1][3]);
#pragma unroll
                for (int nt = 0; nt < 8; nt += 2) {
                    unsigned addr = vbase +
                        ((((g << 4) + vrow) * LVH) + (nt << 3) + ksel) * 2;
                    unsigned b0[2], b1[2];
                    ldmx4t(b0[0], b0[1], b1[0], b1[1], addr);
                    mma16(o[nt],     pa, b0);
                    mma16(o[nt + 1], pa, b1);
                }
            }
        }
    }

    // ---- combine lsum partials + quad reduction ----
    float ls[2];
#pragma unroll
    for (int hh = 0; hh < 2; hh++) {
        ls[hh] = lsum[0][hh] + lsum[1][hh];
        ls[hh] += __shfl_xor_sync(0xffffffffu, ls[hh], 1);
        ls[hh] += __shfl_xor_sync(0xffffffffu, ls[hh], 2);
    }

    __half* Ob = O + ((size_t)(b * SEQ + q0 + w16)) * DIM + h * HDIM;
#pragma unroll
    for (int hh = 0; hh < 2; hh++) {
        float inv = 1.0f / ls[hh];
        int r = lr + (hh << 3);
#pragma unroll
        for (int nt = 0; nt < 8; nt++) {
            *(__half2*)&Ob[(size_t)r * DIM + (nt << 3) + (lc << 1)] =
                __floats2half2_rn(o[nt][(hh << 1)] * inv, o[nt][(hh << 1) + 1] * inv);
        }
    }
}

// ---------------------------------------------------------------------------
// Launch
// ---------------------------------------------------------------------------
extern "C" void kernel_launch(void* const* d_in, const int* in_sizes, int n_in,
                              void* d_out, int out_size)
{
    const float* x  = (const float*)d_in[0];
    const float* Wq = (const float*)d_in[1];
    const float* Wk = (const float*)d_in[2];
    const float* Wv = (const float*)d_in[3];
    const float* Wo = (const float*)d_in[4];
    const float* bo = (const float*)d_in[5];
    float* out = (float*)d_out;

    __half *xh, *wqh, *wkh, *wvh, *woh, *qp, *kp, *vp, *cp;
    cudaGetSymbolAddress((void**)&xh,  gh_x);
    cudaGetSymbolAddress((void**)&wqh, gh_Wq);
    cudaGetSymbolAddress((void**)&wkh, gh_Wk);
    cudaGetSymbolAddress((void**)&wvh, gh_Wv);
    cudaGetSymbolAddress((void**)&woh, gh_Wo);
    cudaGetSymbolAddress((void**)&qp,  g_Q);
    cudaGetSymbolAddress((void**)&kp,  g_K);
    cudaGetSymbolAddress((void**)&vp,  g_V);
    cudaGetSymbolAddress((void**)&cp,  g_C);

    cudaFuncSetAttribute(gemm_qkv, cudaFuncAttributeMaxDynamicSharedMemorySize, GEMM_SMEM);
    cudaFuncSetAttribute(gemm_out, cudaFuncAttributeMaxDynamicSharedMemorySize, GEMM_SMEM);
    cudaFuncSetAttribute(attn_h,   cudaFuncAttributeMaxDynamicSharedMemorySize, ATT_SMEM);

    const int NCONV = XQ + 4 * WQ4;
    convall<<<NCONV / 256, 256>>>(x, Wq, Wk, Wv, Wo, xh, wqh, wkh, wvh, woh);

    gemm_qkv<<<dim3(24, 64), 256, GEMM_SMEM>>>(xh, wqh, wkh, wvh, qp, kp, vp);

    dim3 ga(SEQ / 128, NHEADS, BATCH);
    attn_h<<<ga, 256, ATT_SMEM>>>(qp, kp, vp, cp);

    gemm_out<<<dim3(8, 64), 256, GEMM_SMEM>>>(cp, woh, bo, out);
}

// round 17
// speedup vs baseline: 1.0208x; 1.0208x over previous
#include <cuda_runtime.h>
#include <cuda_fp16.h>
#include <math_constants.h>

#define BATCH  4
#define SEQ    2048
#define DIM    1024
#define NHEADS 16
#define HDIM   64
#define MROWS  (BATCH*SEQ)   // 8192

// ---------------------------------------------------------------------------
// Scratch (no cudaMalloc allowed)
// ---------------------------------------------------------------------------
__device__ __half gh_x [(size_t)MROWS * DIM];
__device__ __half gh_Wq[(size_t)DIM * DIM];
__device__ __half gh_Wk[(size_t)DIM * DIM];
__device__ __half gh_Wv[(size_t)DIM * DIM];
__device__ __half gh_Wo[(size_t)DIM * DIM];
__device__ __half g_Q [(size_t)MROWS * DIM];
__device__ __half g_K [(size_t)MROWS * DIM];
__device__ __half g_V [(size_t)MROWS * DIM];
__device__ __half g_C [(size_t)MROWS * DIM];

// ---------------------------------------------------------------------------
// helpers
// ---------------------------------------------------------------------------
__device__ __forceinline__ void mma16(float c[4], const unsigned a[4], const unsigned b[2]) {
    asm volatile(
        "mma.sync.aligned.m16n8k16.row.col.f32.f16.f16.f32 "
        "{%0,%1,%2,%3}, {%4,%5,%6,%7}, {%8,%9}, {%0,%1,%2,%3};\n"
        : "+f"(c[0]), "+f"(c[1]), "+f"(c[2]), "+f"(c[3])
        : "r"(a[0]), "r"(a[1]), "r"(a[2]), "r"(a[3]), "r"(b[0]), "r"(b[1]));
}
__device__ __forceinline__ void ldmx4(unsigned& r0, unsigned& r1, unsigned& r2, unsigned& r3,
                                      unsigned addr) {
    asm volatile("ldmatrix.sync.aligned.m8n8.x4.shared.b16 {%0,%1,%2,%3}, [%4];"
                 : "=r"(r0), "=r"(r1), "=r"(r2), "=r"(r3) : "r"(addr));
}
__device__ __forceinline__ void ldmx4t(unsigned& r0, unsigned& r1, unsigned& r2, unsigned& r3,
                                       unsigned addr) {
    asm volatile("ldmatrix.sync.aligned.m8n8.x4.trans.shared.b16 {%0,%1,%2,%3}, [%4];"
                 : "=r"(r0), "=r"(r1), "=r"(r2), "=r"(r3) : "r"(addr));
}
__device__ __forceinline__ void cpa16(unsigned dst, const void* src) {
    asm volatile("cp.async.cg.shared.global [%0], [%1], 16;\n" :: "r"(dst), "l"(src));
}
#define CP_COMMIT asm volatile("cp.async.commit_group;\n" ::: "memory")
#define CP_WAIT0  asm volatile("cp.async.wait_group 0;\n" ::: "memory")
#define CP_WAIT1  asm volatile("cp.async.wait_group 1;\n" ::: "memory")
#define CP_WAIT2  asm volatile("cp.async.wait_group 2;\n" ::: "memory")

__device__ __forceinline__ unsigned packh2(float a, float b) {
    unsigned r;
    asm("cvt.rn.f16x2.f32 %0, %1, %2;" : "=r"(r) : "f"(b), "f"(a));
    return r;
}
__device__ __forceinline__ float ex2(float x) {
    float y;
    asm("ex2.approx.ftz.f32 %0, %1;" : "=f"(y) : "f"(x));
    return y;
}

// ---------------------------------------------------------------------------
// one-time fp32->fp16: x + all 4 weights in ONE launch
// ---------------------------------------------------------------------------
#define XQ  (MROWS * DIM / 4)
#define WQ4 (DIM * DIM / 4)
__global__ void convall(const float* __restrict__ x,
                        const float* __restrict__ w0, const float* __restrict__ w1,
                        const float* __restrict__ w2, const float* __restrict__ w3,
                        __half* __restrict__ xh,
                        __half* __restrict__ d0, __half* __restrict__ d1,
                        __half* __restrict__ d2, __half* __restrict__ d3) {
    const int g = blockIdx.x * blockDim.x + threadIdx.x;
    const float* s;
    __half* d;
    int i;
    if (g < XQ) { s = x; d = xh; i = g << 2; }
    else {
        int gg = g - XQ;
        int seg = gg >> 18;
        i = (gg & 0x3FFFF) << 2;
        s = (seg == 0) ? w0 : (seg == 1) ? w1 : (seg == 2) ? w2 : w3;
        d = (seg == 0) ? d0 : (seg == 1) ? d1 : (seg == 2) ? d2 : d3;
    }
    float4 v = *(const float4*)&s[i];
    *(__half2*)&d[i]     = __floats2half2_rn(v.x, v.y);
    *(__half2*)&d[i + 2] = __floats2half2_rn(v.z, v.w);
}

// ---------------------------------------------------------------------------
// GEMM (best-known config): block 128x128, kstep 32, 8 warps (32x64), 3-stage
// cp.async pipeline (WAIT1 steady state), x4 ldmatrix fragments.
// ---------------------------------------------------------------------------
#define LAH 40
#define LBH 136
#define A_SZH (128*LAH)
#define B_SZH (32*LBH)
#define GSTGH (A_SZH+B_SZH)     // 9472 halves
#define GEMM_SMEM (3*GSTGH*2)   // 56832 B

struct GemmCtx {
    int t, warp, lane, wm, wn;
    unsigned s0;
};

__device__ __forceinline__ void gemm_issue(const __half* Ag, const __half* Bg,
                                           unsigned sb, int a_r, int a_c,
                                           int b_r, int b_c, int ko) {
    cpa16(sb + (a_r * LAH + a_c) * 2,             Ag + ko);
    cpa16(sb + (a_r * LAH + a_c + 8) * 2,         Ag + ko + 8);
    cpa16(sb + (A_SZH + b_r * LBH + b_c) * 2,     Bg + (size_t)ko * DIM);
    cpa16(sb + (A_SZH + b_r * LBH + b_c + 8) * 2, Bg + (size_t)ko * DIM + 8);
    CP_COMMIT;
}

__device__ __forceinline__ void gemm_mainloop(
    const __half* __restrict__ Ag, const __half* __restrict__ Bg,
    const GemmCtx& cx, float acc[2][8][4])
{
    const int t = cx.t, lane = cx.lane;
    const int a_r = t >> 1, a_c = (t & 1) << 4;
    const int b_r = t >> 3, b_c = (t & 7) << 4;
    const unsigned s0 = cx.s0;

    gemm_issue(Ag, Bg, s0,             a_r, a_c, b_r, b_c, 0);
    gemm_issue(Ag, Bg, s0 + GSTGH * 2, a_r, a_c, b_r, b_c, 32);

    const int arow = lane & 15;
    const int akof = (lane & 16) >> 1;
    const int brow = (lane & 7) + ((lane >> 3) & 1) * 8;
    const int bsel = (lane >> 4) << 3;

    const int NIT = DIM >> 5;     // 32
    for (int it = 0; it < NIT; ++it) {
        if (it < NIT - 1) { CP_WAIT1; } else { CP_WAIT0; }
        __syncthreads();

        if (it + 2 < NIT) {
            const unsigned sb = s0 + ((it + 2) % 3) * GSTGH * 2;
            gemm_issue(Ag, Bg, sb, a_r, a_c, b_r, b_c, (it + 2) << 5);
        }

        const unsigned abase = s0 + (it % 3) * GSTGH * 2;
        const unsigned bbase = abase + A_SZH * 2;

#pragma unroll
        for (int ch = 0; ch < 2; ch++) {
            const int k0 = ch << 4;
            unsigned af[2][4], bf[8][2];
#pragma unroll
            for (int mt = 0; mt < 2; mt++) {
                unsigned addr = abase +
                    (((cx.wm + (mt << 4) + arow) * LAH) + k0 + akof) * 2;
                ldmx4(af[mt][0], af[mt][1], af[mt][2], af[mt][3], addr);
            }
#pragma unroll
            for (int nt = 0; nt < 8; nt += 2) {
                unsigned addr = bbase +
                    (((k0 + brow) * LBH) + cx.wn + (nt << 3) + bsel) * 2;
                ldmx4t(bf[nt][0], bf[nt][1], bf[nt + 1][0], bf[nt + 1][1], addr);
            }
#pragma unroll
            for (int mt = 0; mt < 2; mt++)
#pragma unroll
                for (int nt = 0; nt < 8; nt++)
                    mma16(acc[mt][nt], af[mt], bf[nt]);
        }
    }
}

// ---- fused QKV projection: grid (24, 64). Q pre-scaled by 0.125*log2(e).
__global__ __launch_bounds__(256, 2)
void gemm_qkv(const __half* __restrict__ xh,
              const __half* __restrict__ Wq, const __half* __restrict__ Wk,
              const __half* __restrict__ Wv,
              __half* __restrict__ Qo, __half* __restrict__ Ko,
              __half* __restrict__ Vo)
{
    extern __shared__ __half sh[];
    GemmCtx cx;
    cx.t = threadIdx.x; cx.warp = cx.t >> 5; cx.lane = cx.t & 31;
    cx.wm = (cx.warp >> 1) << 5; cx.wn = (cx.warp & 1) << 6;
    cx.s0 = (unsigned)__cvta_generic_to_shared(sh);

    const int widx = blockIdx.x >> 3;
    const int col0 = (blockIdx.x & 7) << 7;
    const int row0 = blockIdx.y << 7;
    const __half* B = (widx == 0) ? Wq : (widx == 1) ? Wk : Wv;
    __half*       C = (widx == 0) ? Qo : (widx == 1) ? Ko : Vo;
    const float scale = (widx == 0) ? 0.125f * 1.44269504f : 1.0f;

    float acc[2][8][4];
#pragma unroll
    for (int mt = 0; mt < 2; mt++)
#pragma unroll
        for (int nt = 0; nt < 8; nt++)
#pragma unroll
            for (int i = 0; i < 4; i++) acc[mt][nt][i] = 0.f;

    const int a_r = cx.t >> 1, a_c = (cx.t & 1) << 4;
    const int b_r = cx.t >> 3, b_c = (cx.t & 7) << 4;
    gemm_mainloop(xh + (size_t)(row0 + a_r) * DIM + a_c,
                  B + (size_t)b_r * DIM + col0 + b_c, cx, acc);

    const int lr = cx.lane >> 2, lc = cx.lane & 3;
#pragma unroll
    for (int nt = 0; nt < 8; nt++) {
        const int c = col0 + cx.wn + (nt << 3) + (lc << 1);
#pragma unroll
        for (int mt = 0; mt < 2; mt++) {
            const int r = row0 + cx.wm + (mt << 4) + lr;
#pragma unroll
            for (int hh = 0; hh < 2; hh++) {
                float a0 = acc[mt][nt][(hh << 1)] * scale;
                float a1 = acc[mt][nt][(hh << 1) + 1] * scale;
                *(__half2*)&C[(size_t)(r + (hh << 3)) * DIM + c] =
                    __floats2half2_rn(a0, a1);
            }
        }
    }
}

// ---- output projection: float out + bias. grid (8, 64)
__global__ __launch_bounds__(256, 2)
void gemm_out(const __half* __restrict__ A, const __half* __restrict__ B,
              const float* __restrict__ bias, float* __restrict__ Cf)
{
    extern __shared__ __half sh[];
    GemmCtx cx;
    cx.t = threadIdx.x; cx.warp = cx.t >> 5; cx.lane = cx.t & 31;
    cx.wm = (cx.warp >> 1) << 5; cx.wn = (cx.warp & 1) << 6;
    cx.s0 = (unsigned)__cvta_generic_to_shared(sh);

    const int col0 = blockIdx.x << 7;
    const int row0 = blockIdx.y << 7;

    float acc[2][8][4];
#pragma unroll
    for (int mt = 0; mt < 2; mt++)
#pragma unroll
        for (int nt = 0; nt < 8; nt++)
#pragma unroll
            for (int i = 0; i < 4; i++) acc[mt][nt][i] = 0.f;

    const int a_r = cx.t >> 1, a_c = (cx.t & 1) << 4;
    const int b_r = cx.t >> 3, b_c = (cx.t & 7) << 4;
    gemm_mainloop(A + (size_t)(row0 + a_r) * DIM + a_c,
                  B + (size_t)b_r * DIM + col0 + b_c, cx, acc);

    const int lr = cx.lane >> 2, lc = cx.lane & 3;
#pragma unroll
    for (int nt = 0; nt < 8; nt++) {
        const int c = col0 + cx.wn + (nt << 3) + (lc << 1);
        const float bx = bias[c], by = bias[c + 1];
#pragma unroll
        for (int mt = 0; mt < 2; mt++) {
            const int r = row0 + cx.wm + (mt << 4) + lr;
#pragma unroll
            for (int hh = 0; hh < 2; hh++) {
                *(float2*)&Cf[(size_t)(r + (hh << 3)) * DIM + c] =
                    make_float2(acc[mt][nt][(hh << 1)] + bx,
                                acc[mt][nt][(hh << 1) + 1] + by);
            }
        }
    }
}

// ---------------------------------------------------------------------------
// fp16 flash attention (best-known R15 config): no-max base-2 softmax,
// 128 q-rows/block, 8 warps, 3-stage 64-key KV pipeline, x4 ldmatrix,
// lsum split into 2 partial accumulators per row-half.
// ---------------------------------------------------------------------------
#define LKH 72
#define LVH 72
#define QSZH (128*LKH)
#define KSZH (64*LKH)
#define VSZH (64*LVH)
#define STGH (KSZH+VSZH)
#define ATT_SMEM ((QSZH + 3*STGH)*2)   // 73728 B

__global__ __launch_bounds__(256, 2)
void attn_h(const __half* __restrict__ Q, const __half* __restrict__ K,
            const __half* __restrict__ V, __half* __restrict__ O)
{
    extern __shared__ __half sh[];

    const int qt = (gridDim.x - 1) - blockIdx.x;
    const int h  = blockIdx.y, b = blockIdx.z;
    const int t    = threadIdx.x;
    const int warp = t >> 5, lane = t & 31;
    const int lr   = lane >> 2, lc = lane & 3;
    const int q0   = qt << 7, w16 = warp << 4;
    const int wrow0 = q0 + w16;

    const __half* Kb = K + (size_t)b * SEQ * DIM + h * HDIM;
    const __half* Vb = V + (size_t)b * SEQ * DIM + h * HDIM;
    const unsigned smu = (unsigned)__cvta_generic_to_shared(sh);

    const int kvr = t >> 2, kvc = (t & 3) << 4;
    const int last = 2 * qt + 1;

    {
        const __half* Qb = Q + ((size_t)(b * SEQ + q0)) * DIM + h * HDIM;
#pragma unroll
        for (int j = 0; j < 4; j++) {
            int id = t + (j << 8);
            int r = id >> 3, c = (id & 7) << 3;
            cpa16(smu + (r * LKH + c) * 2, &Qb[(size_t)r * DIM + c]);
        }
        CP_COMMIT;
#pragma unroll
        for (int s = 0; s < 2; s++) {
            const __half* Kt = Kb + ((size_t)(s << 6)) * DIM;
            const __half* Vt = Vb + ((size_t)(s << 6)) * DIM;
            const unsigned sb = smu + (QSZH + s * STGH) * 2;
            cpa16(sb + (kvr * LKH + kvc) * 2,            &Kt[(size_t)kvr * DIM + kvc]);
            cpa16(sb + (kvr * LKH + kvc + 8) * 2,        &Kt[(size_t)kvr * DIM + kvc + 8]);
            cpa16(sb + (KSZH + kvr * LVH + kvc) * 2,     &Vt[(size_t)kvr * DIM + kvc]);
            cpa16(sb + (KSZH + kvr * LVH + kvc + 8) * 2, &Vt[(size_t)kvr * DIM + kvc + 8]);
            CP_COMMIT;
        }
        CP_WAIT2;
    }
    __syncthreads();

    // Q A-fragments (ldmatrix.x4)
    unsigned qa[4][4];
    {
        const int arow = lane & 15;
        const int akof = (lane & 16) >> 1;
#pragma unroll
        for (int ch = 0; ch < 4; ch++) {
            unsigned addr = smu + (((w16 + arow) * LKH) + (ch << 4) + akof) * 2;
            ldmx4(qa[ch][0], qa[ch][1], qa[ch][2], qa[ch][3], addr);
        }
    }

    const int krow8 = lane & 7;
    const int ksel  = (lane >> 4) << 3;
    const int kk8   = lane & 8;
    const int vrow  = (lane & 7) + ((lane >> 3) & 1) * 8;

    float o[8][4];
#pragma unroll
    for (int nt = 0; nt < 8; nt++)
#pragma unroll
        for (int i = 0; i < 4; i++) o[nt][i] = 0.f;
    float lsum[2][2] = {{0.f, 0.f}, {0.f, 0.f}};   // [nt&1][row-half]

    for (int kt = 0; kt <= last; ++kt) {
        if (kt < last) { CP_WAIT1; } else { CP_WAIT0; }
        __syncthreads();

        if (kt + 2 <= last) {
            const __half* Kt = Kb + ((size_t)((kt + 2) << 6)) * DIM;
            const __half* Vt = Vb + ((size_t)((kt + 2) << 6)) * DIM;
            const unsigned sb = smu + (QSZH + ((kt + 2) % 3) * STGH) * 2;
            cpa16(sb + (kvr * LKH + kvc) * 2,            &Kt[(size_t)kvr * DIM + kvc]);
            cpa16(sb + (kvr * LKH + kvc + 8) * 2,        &Kt[(size_t)kvr * DIM + kvc + 8]);
            cpa16(sb + (KSZH + kvr * LVH + kvc) * 2,     &Vt[(size_t)kvr * DIM + kvc]);
            cpa16(sb + (KSZH + kvr * LVH + kvc + 8) * 2, &Vt[(size_t)kvr * DIM + kvc + 8]);
            CP_COMMIT;
        }

        const unsigned kbase = smu + (QSZH + (kt % 3) * STGH) * 2;
        const unsigned vbase = kbase + KSZH * 2;

        if ((kt << 6) <= wrow0 + 15) {
            // ---- S = Q K^T ----
            float sc[8][4];
#pragma unroll
            for (int nt = 0; nt < 8; nt++)
#pragma unroll
                for (int i = 0; i < 4; i++) sc[nt][i] = 0.f;
#pragma unroll
            for (int ch = 0; ch < 4; ch++) {
                const int k0 = ch << 4;
#pragma unroll
                for (int nt = 0; nt < 8; nt += 2) {
                    unsigned addr = kbase +
                        ((((nt << 3) + ksel + krow8) * LKH) + k0 + kk8) * 2;
                    unsigned b0[2], b1[2];
                    ldmx4(b0[0], b0[1], b1[0], b1[1], addr);
                    mma16(sc[nt],     qa[ch], b0);
                    mma16(sc[nt + 1], qa[ch], b1);
                }
            }

            // ---- causal mask ----
            if ((kt << 6) + 63 > wrow0) {
#pragma unroll
                for (int nt = 0; nt < 8; nt++)
#pragma unroll
                    for (int i = 0; i < 4; i++) {
                        int rr = wrow0 + lr + ((i >> 1) << 3);
                        int cc = (kt << 6) + (nt << 3) + (lc << 1) + (i & 1);
                        if (cc > rr) sc[nt][i] = -CUDART_INF_F;
                    }
            }

            // ---- p = 2^score; lsum via 2 independent partials ----
#pragma unroll
            for (int nt = 0; nt < 8; nt++)
#pragma unroll
                for (int i = 0; i < 4; i++) {
                    float p = ex2(sc[nt][i]);
                    sc[nt][i] = p;
                    lsum[nt & 1][i >> 1] += p;
                }

            // ---- O += P V ----
#pragma unroll
            for (int g = 0; g < 4; g++) {
                unsigned pa[4];
                pa[0] = packh2(sc[2 * g][0],     sc[2 * g][1]);
                pa[1] = packh2(sc[2 * g][2],     sc[2 * g][3]);
                pa[2] = packh2(sc[2 * g + 1][0], sc[2 * g + 1][1]);
                pa[3] = packh2(sc[2 * g + 1][2], sc[2 * g + 1][3]);
#pragma unroll
                for (int nt = 0; nt < 8; nt += 2) {
                    unsigned addr = vbase +
                        ((((g << 4) + vrow) * LVH) + (nt << 3) + ksel) * 2;
                    unsigned b0[2], b1[2];
                    ldmx4t(b0[0], b0[1], b1[0], b1[1], addr);
                    mma16(o[nt],     pa, b0);
                    mma16(o[nt + 1], pa, b1);
                }
            }
        }
    }

    // ---- combine lsum partials + quad reduction ----
    float ls[2];
#pragma unroll
    for (int hh = 0; hh < 2; hh++) {
        ls[hh] = lsum[0][hh] + lsum[1][hh];
        ls[hh] += __shfl_xor_sync(0xffffffffu, ls[hh], 1);
        ls[hh] += __shfl_xor_sync(0xffffffffu, ls[hh], 2);
    }

    __half* Ob = O + ((size_t)(b * SEQ + q0 + w16)) * DIM + h * HDIM;
#pragma unroll
    for (int hh = 0; hh < 2; hh++) {
        float inv = 1.0f / ls[hh];
        int r = lr + (hh << 3);
#pragma unroll
        for (int nt = 0; nt < 8; nt++) {
            *(__half2*)&Ob[(size_t)r * DIM + (nt << 3) + (lc << 1)] =
                __floats2half2_rn(o[nt][(hh << 1)] * inv, o[nt][(hh << 1) + 1] * inv);
        }
    }
}

// ---------------------------------------------------------------------------
// Launch
// ---------------------------------------------------------------------------
extern "C" void kernel_launch(void* const* d_in, const int* in_sizes, int n_in,
                              void* d_out, int out_size)
{
    const float* x  = (const float*)d_in[0];
    const float* Wq = (const float*)d_in[1];
    const float* Wk = (const float*)d_in[2];
    const float* Wv = (const float*)d_in[3];
    const float* Wo = (const float*)d_in[4];
    const float* bo = (const float*)d_in[5];
    float* out = (float*)d_out;

    __half *xh, *wqh, *wkh, *wvh, *woh, *qp, *kp, *vp, *cp;
    cudaGetSymbolAddress((void**)&xh,  gh_x);
    cudaGetSymbolAddress((void**)&wqh, gh_Wq);
    cudaGetSymbolAddress((void**)&wkh, gh_Wk);
    cudaGetSymbolAddress((void**)&wvh, gh_Wv);
    cudaGetSymbolAddress((void**)&woh, gh_Wo);
    cudaGetSymbolAddress((void**)&qp,  g_Q);
    cudaGetSymbolAddress((void**)&kp,  g_K);
    cudaGetSymbolAddress((void**)&vp,  g_V);
    cudaGetSymbolAddress((void**)&cp,  g_C);

    cudaFuncSetAttribute(gemm_qkv, cudaFuncAttributeMaxDynamicSharedMemorySize, GEMM_SMEM);
    cudaFuncSetAttribute(gemm_out, cudaFuncAttributeMaxDynamicSharedMemorySize, GEMM_SMEM);
    cudaFuncSetAttribute(attn_h,   cudaFuncAttributeMaxDynamicSharedMemorySize, ATT_SMEM);

    const int NCONV = XQ + 4 * WQ4;
    convall<<<NCONV / 256, 256>>>(x, Wq, Wk, Wv, Wo, xh, wqh, wkh, wvh, woh);

    gemm_qkv<<<dim3(24, 64), 256, GEMM_SMEM>>>(xh, wqh, wkh, wvh, qp, kp, vp);

    dim3 ga(SEQ / 128, NHEADS, BATCH);
    attn_h<<<ga, 256, ATT_SMEM>>>(qp, kp, vp, cp);

    gemm_out<<<dim3(8, 64), 256, GEMM_SMEM>>>(cp, woh, bo, out);
}